// round 6
// baseline (speedup 1.0000x reference)
#include <cuda_runtime.h>

// LSTM: B=2048, T=512, F=64, H=128. Gate order i,f,g,o. out[b][t][h] fp32.
// Each block owns MB batch rows for the entire time loop (rows are independent).

#define T_DIM 512
#define F_DIM 64
#define H_DIM 128
#define G_DIM 512              // 4*H
#define MB    8                // batch rows per block
#define NTH   512              // threads per block, thread j -> gate column j
#define KREG  96               // unified-k rows held in registers (Wx 0..63 + Wh 0..31)
#define KSMEM 96               // Wh rows 32..127 held in smem
#define KTOT  (F_DIM + H_DIM)  // 192
#define PAD   12               // activation row pad (floats): 48B, 16B-aligned

__device__ __forceinline__ float sigmoidf_(float v) {
    return 1.0f / (1.0f + __expf(-v));
}

__global__ __launch_bounds__(NTH, 1)
void lstm_fused(const float* __restrict__ x,
                const float* __restrict__ Wx,
                const float* __restrict__ Wh,
                const float* __restrict__ bias,
                float* __restrict__ out)
{
    extern __shared__ float sm[];
    float* sW = sm;                          // [KSMEM][G_DIM]   192 KB
    float* sZ = sW + KSMEM * G_DIM;          // [MB][G_DIM]       16 KB
    float* sC = sZ + MB * G_DIM;             // [MB][H_DIM]        4 KB
    float* sA = sC + MB * H_DIM;             // [KTOT][PAD]        9 KB (transposed acts)

    const int tid = threadIdx.x;
    const int j = tid;                       // gate column 0..511
    const long b0 = (long)blockIdx.x * MB;

    // ---- load weights ----
    float WR[KREG];
    #pragma unroll
    for (int q = 0; q < F_DIM; q++) WR[q] = Wx[q * G_DIM + j];
    #pragma unroll
    for (int q = 0; q < KREG - F_DIM; q++) WR[F_DIM + q] = Wh[q * G_DIM + j];
    for (int kk = 0; kk < KSMEM; kk++)
        sW[kk * G_DIM + j] = Wh[(KREG - F_DIM + kk) * G_DIM + j];
    const float bj = bias[j];

    // ---- zero state ----
    for (int i = tid; i < MB * H_DIM; i += NTH) sC[i] = 0.0f;
    for (int i = tid; i < KTOT * PAD; i += NTH) sA[i] = 0.0f;

    // x loader mapping: thread -> (row, feature), one element per step
    const int xr = tid >> 6;                 // 0..7
    const int xk = tid & 63;                 // 0..63
    const float* xptr = x + (b0 + xr) * (long)(T_DIM * F_DIM) + xk;
    float xreg = xptr[0];

    __syncthreads();

    for (int t = 0; t < T_DIM; t++) {
        // stage x_t into transposed activation buffer (k rows 0..63)
        sA[xk * PAD + xr] = xreg;
        __syncthreads();                     // [A] x + h(prev gate) visible
        if (t + 1 < T_DIM) xreg = xptr[(t + 1) * F_DIM];  // prefetch under FMA loop

        float acc[MB];
        #pragma unroll
        for (int r = 0; r < MB; r++) acc[r] = bj;

        // register-weight region: k = 0..95 (Wx all rows, Wh rows 0..31)
        #pragma unroll
        for (int k = 0; k < KREG; k++) {
            float4 a0 = *(const float4*)(sA + k * PAD);
            float4 a1 = *(const float4*)(sA + k * PAD + 4);
            float w = WR[k];
            acc[0] = fmaf(w, a0.x, acc[0]);
            acc[1] = fmaf(w, a0.y, acc[1]);
            acc[2] = fmaf(w, a0.z, acc[2]);
            acc[3] = fmaf(w, a0.w, acc[3]);
            acc[4] = fmaf(w, a1.x, acc[4]);
            acc[5] = fmaf(w, a1.y, acc[5]);
            acc[6] = fmaf(w, a1.z, acc[6]);
            acc[7] = fmaf(w, a1.w, acc[7]);
        }
        // smem-weight region: k = 96..191 (Wh rows 32..127), coalesced weight loads
        #pragma unroll 8
        for (int k = KREG; k < KTOT; k++) {
            float4 a0 = *(const float4*)(sA + k * PAD);
            float4 a1 = *(const float4*)(sA + k * PAD + 4);
            float w = sW[(k - KREG) * G_DIM + j];
            acc[0] = fmaf(w, a0.x, acc[0]);
            acc[1] = fmaf(w, a0.y, acc[1]);
            acc[2] = fmaf(w, a0.z, acc[2]);
            acc[3] = fmaf(w, a0.w, acc[3]);
            acc[4] = fmaf(w, a1.x, acc[4]);
            acc[5] = fmaf(w, a1.y, acc[5]);
            acc[6] = fmaf(w, a1.z, acc[6]);
            acc[7] = fmaf(w, a1.w, acc[7]);
        }

        #pragma unroll
        for (int r = 0; r < MB; r++) sZ[r * G_DIM + j] = acc[r];
        __syncthreads();                     // [B] z visible

        // gate combine: MB*H = 1024 items, 2 per thread
        #pragma unroll
        for (int it = 0; it < (MB * H_DIM) / NTH; it++) {
            int idx = tid + it * NTH;
            int r  = idx >> 7;
            int jh = idx & (H_DIM - 1);
            const float* zr = sZ + r * G_DIM;
            float ig = sigmoidf_(zr[jh]);
            float fg = sigmoidf_(zr[jh + H_DIM]);
            float gg = tanhf(zr[jh + 2 * H_DIM]);
            float og = sigmoidf_(zr[jh + 3 * H_DIM]);
            float c = fmaf(fg, sC[r * H_DIM + jh], ig * gg);
            sC[r * H_DIM + jh] = c;
            float h = og * tanhf(c);
            sA[(F_DIM + jh) * PAD + r] = h;  // k rows 64..191
            out[(b0 + r) * (long)(T_DIM * H_DIM) + (long)t * H_DIM + jh] = h;
        }
        // no barrier here: next iter's x-write targets k rows 0..63 (disjoint from
        // gate writes), and barrier [A] orders gate's h writes before the FMA reads.
    }
}

extern "C" void kernel_launch(void* const* d_in, const int* in_sizes, int n_in,
                              void* d_out, int out_size) {
    const float* x  = (const float*)d_in[0];   // [B,T,F]
    const float* Wx = (const float*)d_in[1];   // [F,4H]
    const float* Wh = (const float*)d_in[2];   // [H,4H]
    const float* b  = (const float*)d_in[3];   // [4H]
    float* out = (float*)d_out;                // [B,T,H]

    const int Bdim = in_sizes[0] / (T_DIM * F_DIM);   // 2048
    const size_t smem = (size_t)(KSMEM * G_DIM + MB * G_DIM + MB * H_DIM + KTOT * PAD)
                        * sizeof(float);              // 226,304 B

    cudaFuncSetAttribute(lstm_fused, cudaFuncAttributeMaxDynamicSharedMemorySize,
                         (int)smem);

    dim3 grid(Bdim / MB);   // 256 blocks
    dim3 block(NTH);
    lstm_fused<<<grid, block, smem>>>(x, Wx, Wh, b, out);
}

// round 8
// speedup vs baseline: 2.3679x; 2.3679x over previous
#include <cuda_runtime.h>
#include <cuda_bf16.h>
#include <cstdint>

// LSTM B=2048,T=512,F=64,H=128 via mma.sync bf16 (3-term split) + 2-CTA cluster.
// Cluster = 32 batch rows. CTA rank r owns gate cols for h-cols [64r, 64r+64),
// gate-interleaved: local n (0..255) -> hcol 64r + (n>>2), gate n&3.
// A tile [32 rows][192 k] (k: 0-63 = x_t, 64-191 = h) bf16 hi+lo, ldmatrix layout.

#define T_DIM 512
#define F_DIM 64
#define H_DIM 128
#define TFX   (T_DIM * F_DIM)
#define THX   (T_DIM * H_DIM)
#define NTH   256

#define OFF_WHI 0
#define OFF_WLO 98304
#define OFF_AHI 196608
#define OFF_ALO 208896
#define OFF_SHI 221184
#define OFF_SLO 225280
#define SMEM_TOTAL 229376     // <= 232448 max dynamic smem

typedef uint32_t u32;
typedef unsigned long long u64;

static __device__ __forceinline__ u32 smaddr(const void* p) {
    u32 a;
    asm("{ .reg .u64 t; cvta.to.shared.u64 t, %1; cvt.u32.u64 %0, t; }" : "=r"(a) : "l"(p));
    return a;
}
static __device__ __forceinline__ u32 ctarank() {
    u32 r; asm("mov.u32 %0, %%cluster_ctarank;" : "=r"(r)); return r;
}
static __device__ __forceinline__ u32 mapa_(u32 a, u32 r) {
    u32 d; asm("mapa.shared::cluster.u32 %0, %1, %2;" : "=r"(d) : "r"(a), "r"(r)); return d;
}
static __device__ __forceinline__ void csync() {
    asm volatile("barrier.cluster.arrive.aligned;" ::: "memory");
    asm volatile("barrier.cluster.wait.aligned;" ::: "memory");
}
static __device__ __forceinline__ void ldm4(u32& a, u32& b, u32& c, u32& d, u32 ad) {
    asm volatile("ldmatrix.sync.aligned.m8n8.x4.shared.b16 {%0,%1,%2,%3}, [%4];"
                 : "=r"(a), "=r"(b), "=r"(c), "=r"(d) : "r"(ad));
}
static __device__ __forceinline__ void ldm2(u32& a, u32& b, u32 ad) {
    asm volatile("ldmatrix.sync.aligned.m8n8.x2.shared.b16 {%0,%1}, [%2];"
                 : "=r"(a), "=r"(b) : "r"(ad));
}
static __device__ __forceinline__ void mma_bf16(float& c0, float& c1, float& c2, float& c3,
                                                u32 a0, u32 a1, u32 a2, u32 a3, u32 b0, u32 b1) {
    asm volatile(
        "mma.sync.aligned.m16n8k16.row.col.f32.bf16.bf16.f32 "
        "{%0,%1,%2,%3}, {%4,%5,%6,%7}, {%8,%9}, {%0,%1,%2,%3};"
        : "+f"(c0), "+f"(c1), "+f"(c2), "+f"(c3)
        : "r"(a0), "r"(a1), "r"(a2), "r"(a3), "r"(b0), "r"(b1));
}
static __device__ __forceinline__ void st_rem64(u32 ad, u64 v) {
    asm volatile("st.shared::cluster.b64 [%0], %1;" :: "r"(ad), "l"(v) : "memory");
}
static __device__ __forceinline__ float sigf(float v) {
    return __fdividef(1.0f, 1.0f + __expf(-v));
}
static __device__ __forceinline__ float tanhf_(float v) {
    return __fdividef(2.0f, 1.0f + __expf(-2.0f * v)) - 1.0f;
}
static __device__ __forceinline__ u32 cat2(__nv_bfloat16 a, __nv_bfloat16 b) {
    return (u32)__bfloat16_as_ushort(a) | ((u32)__bfloat16_as_ushort(b) << 16);
}
static __device__ __forceinline__ void split8(const float* v, uint4& h, uint4& l) {
    __nv_bfloat16 bh[8];
    float rr[8];
#pragma unroll
    for (int i = 0; i < 8; i++) {
        bh[i] = __float2bfloat16(v[i]);
        rr[i] = v[i] - __bfloat162float(bh[i]);
    }
    h.x = cat2(bh[0], bh[1]); h.y = cat2(bh[2], bh[3]);
    h.z = cat2(bh[4], bh[5]); h.w = cat2(bh[6], bh[7]);
    l.x = cat2(__float2bfloat16(rr[0]), __float2bfloat16(rr[1]));
    l.y = cat2(__float2bfloat16(rr[2]), __float2bfloat16(rr[3]));
    l.z = cat2(__float2bfloat16(rr[4]), __float2bfloat16(rr[5]));
    l.w = cat2(__float2bfloat16(rr[6]), __float2bfloat16(rr[7]));
}

__global__ void __cluster_dims__(2, 1, 1) __launch_bounds__(NTH, 1)
lstm_mma(const float* __restrict__ x, const float* __restrict__ Wx,
         const float* __restrict__ Wh, const float* __restrict__ bias,
         float* __restrict__ out)
{
    extern __shared__ char smc[];
    const u32 sb = smaddr(smc);
    const int tid = threadIdx.x, w = tid >> 5, lane = tid & 31;
    const u32 rank = ctarank();
    const long b0 = (long)(blockIdx.x >> 1) * 32;

    // ---- W load + hi/lo split into ldmatrix-swizzled [n][k] layout ----
    for (int idx = tid; idx < 192 * 256; idx += NTH) {
        int k = idx >> 8, nn = idx & 255;
        int col = (nn & 3) * 128 + 64 * (int)rank + (nn >> 2);
        float wv = (k < F_DIM) ? Wx[k * 512 + col] : Wh[(k - F_DIM) * 512 + col];
        __nv_bfloat16 bh = __float2bfloat16(wv);
        __nv_bfloat16 bl = __float2bfloat16(wv - __bfloat162float(bh));
        u32 off = (u32)(nn * 384 + 16 * ((k >> 3) ^ (nn & 7)) + (k & 7) * 2);
        *(__nv_bfloat16*)(smc + OFF_WHI + off) = bh;
        *(__nv_bfloat16*)(smc + OFF_WLO + off) = bl;
    }
    // zero A tiles + h stage
    for (int i = tid; i < (SMEM_TOTAL - OFF_AHI) / 8; i += NTH)
        ((u64*)(smc + OFF_AHI))[i] = 0ull;
    __syncthreads();

    // ---- pass2 thread mapping (A writers) ----
    const int prow = tid >> 3, pj = tid & 7;
    const float* xbase = x + (b0 + prow) * (long)TFX + 8 * pj;
    const u32 offx = (u32)(prow * 384 + 16 * (pj ^ (prow & 7)));
    const u32 offh = (u32)(prow * 384 + 16 * (((8 + 8 * (int)rank + pj)) ^ (prow & 7)));
    const u32 peerAhi = mapa_(sb + OFF_AHI, rank ^ 1) + offh;
    const u32 peerAlo = mapa_(sb + OFF_ALO, rank ^ 1) + offh;

    // x(0) insert
    {
        float4 q0 = *(const float4*)(xbase);
        float4 q1 = *(const float4*)(xbase + 4);
        float v[8] = {q0.x, q0.y, q0.z, q0.w, q1.x, q1.y, q1.z, q1.w};
        uint4 xh, xl;
        split8(v, xh, xl);
        *(uint4*)(smc + OFF_AHI + offx) = xh;
        *(uint4*)(smc + OFF_ALO + offx) = xl;
    }

    // ---- MMA fragment addressing ----
    const int amat = lane >> 3, aidx = lane & 7;
    const int arow = ((amat & 1) << 3) + aidx;     // rows 0..15 (+16 for mi=1)
    const int aksel = amat >> 1;                   // kb = 2*ks + aksel
    const int a7 = arow & 7;
    const u32 aob0 = sb + OFF_AHI + (u32)(arow * 384);
    const u32 aob1 = sb + OFF_AHI + (u32)((arow + 16) * 384);

    const int bl_ = lane & 15;
    const int brin = bl_ & 7;
    const int bksel = bl_ >> 3;
    u32 bob[4];
#pragma unroll
    for (int nj = 0; nj < 4; nj++)
        bob[nj] = sb + OFF_WHI + (u32)((32 * w + 8 * nj + brin) * 384);

    // ---- epilogue mapping + bias + c state ----
    const int q = lane >> 2, t4 = lane & 3, rs = t4 & 1, jb2 = t4 >> 1;
    float bi[4], bff[4], bg[4], bo[4];
#pragma unroll
    for (int nj = 0; nj < 4; nj++) {
        int jl = 8 * w + 2 * nj + jb2;
        int cb = 64 * (int)rank + jl;
        bi[nj]  = bias[cb];
        bff[nj] = bias[128 + cb];
        bg[nj]  = bias[256 + cb];
        bo[nj]  = bias[384 + cb];
    }
    float cst[2][4];
#pragma unroll
    for (int mi = 0; mi < 2; mi++)
#pragma unroll
        for (int nj = 0; nj < 4; nj++) cst[mi][nj] = 0.0f;

    for (int t = 0; t < T_DIM; t++) {
        csync();    // A(t) complete cluster-wide (peer h + local x/h writes)

        // prefetch x(t+1) under the MMA
        float xv[8];
        if (t + 1 < T_DIM) {
            float4 q0 = *(const float4*)(xbase + (t + 1) * F_DIM);
            float4 q1 = *(const float4*)(xbase + (t + 1) * F_DIM + 4);
            xv[0] = q0.x; xv[1] = q0.y; xv[2] = q0.z; xv[3] = q0.w;
            xv[4] = q1.x; xv[5] = q1.y; xv[6] = q1.z; xv[7] = q1.w;
        }

        float acc[2][4][4];
#pragma unroll
        for (int mi = 0; mi < 2; mi++)
#pragma unroll
            for (int nj = 0; nj < 4; nj++)
#pragma unroll
                for (int e = 0; e < 4; e++) acc[mi][nj][e] = 0.0f;

#pragma unroll
        for (int ks = 0; ks < 12; ks++) {
            const u32 swA = 16u * (u32)((2 * ks + aksel) ^ a7);
            u32 Ah0[4], Ah1[4], Al0[4], Al1[4];
            ldm4(Ah0[0], Ah0[1], Ah0[2], Ah0[3], aob0 + swA);
            ldm4(Ah1[0], Ah1[1], Ah1[2], Ah1[3], aob1 + swA);
            ldm4(Al0[0], Al0[1], Al0[2], Al0[3], aob0 + swA + 12288);
            ldm4(Al1[0], Al1[1], Al1[2], Al1[3], aob1 + swA + 12288);
            const u32 swB = 16u * (u32)((2 * ks + bksel) ^ brin);
            u32 Bh[4][2], Bl[4][2];
#pragma unroll
            for (int nj = 0; nj < 4; nj++) {
                ldm2(Bh[nj][0], Bh[nj][1], bob[nj] + swB);
                ldm2(Bl[nj][0], Bl[nj][1], bob[nj] + swB + 98304);
            }
#pragma unroll
            for (int nj = 0; nj < 4; nj++) {
                mma_bf16(acc[0][nj][0], acc[0][nj][1], acc[0][nj][2], acc[0][nj][3],
                         Ah0[0], Ah0[1], Ah0[2], Ah0[3], Bh[nj][0], Bh[nj][1]);
                mma_bf16(acc[1][nj][0], acc[1][nj][1], acc[1][nj][2], acc[1][nj][3],
                         Ah1[0], Ah1[1], Ah1[2], Ah1[3], Bh[nj][0], Bh[nj][1]);
                mma_bf16(acc[0][nj][0], acc[0][nj][1], acc[0][nj][2], acc[0][nj][3],
                         Ah0[0], Ah0[1], Ah0[2], Ah0[3], Bl[nj][0], Bl[nj][1]);
                mma_bf16(acc[1][nj][0], acc[1][nj][1], acc[1][nj][2], acc[1][nj][3],
                         Ah1[0], Ah1[1], Ah1[2], Ah1[3], Bl[nj][0], Bl[nj][1]);
                mma_bf16(acc[0][nj][0], acc[0][nj][1], acc[0][nj][2], acc[0][nj][3],
                         Al0[0], Al0[1], Al0[2], Al0[3], Bh[nj][0], Bh[nj][1]);
                mma_bf16(acc[1][nj][0], acc[1][nj][1], acc[1][nj][2], acc[1][nj][3],
                         Al1[0], Al1[1], Al1[2], Al1[3], Bh[nj][0], Bh[nj][1]);
            }
        }

        // ---- epilogue pass 1: gates from register fragments via shfl ----
#pragma unroll
        for (int mi = 0; mi < 2; mi++) {
#pragma unroll
            for (int nj = 0; nj < 4; nj++) {
                float v0 = acc[mi][nj][0], v1 = acc[mi][nj][1];
                float v2 = acc[mi][nj][2], v3 = acc[mi][nj][3];
                float p0 = __shfl_xor_sync(0xffffffffu, v0, 1);
                float p1 = __shfl_xor_sync(0xffffffffu, v1, 1);
                float p2 = __shfl_xor_sync(0xffffffffu, v2, 1);
                float p3 = __shfl_xor_sync(0xffffffffu, v3, 1);
                float zi = rs ? p2 : v0;
                float zf = rs ? p3 : v1;
                float zg = rs ? v2 : p0;
                float zo = rs ? v3 : p1;
                float ig = sigf(zi + bi[nj]);
                float fg = sigf(zf + bff[nj]);
                float gg = tanhf_(zg + bg[nj]);
                float og = sigf(zo + bo[nj]);
                float cn = fmaf(fg, cst[mi][nj], ig * gg);
                cst[mi][nj] = cn;
                float h = og * tanhf_(cn);
                int jl = 8 * w + 2 * nj + jb2;
                int row = q + 8 * rs + 16 * mi;
                out[(b0 + row) * (long)THX + (long)t * H_DIM + 64 * (int)rank + jl] = h;
                __nv_bfloat16 hb = __float2bfloat16(h);
                __nv_bfloat16 hr = __float2bfloat16(h - __bfloat162float(hb));
                *(__nv_bfloat16*)(smc + OFF_SHI + (row * 64 + jl) * 2) = hb;
                *(__nv_bfloat16*)(smc + OFF_SLO + (row * 64 + jl) * 2) = hr;
            }
        }

        csync();    // all cluster MMA reads of A(t) done; stage visible locally

        // ---- pass 2: build A(t+1) ----
        if (t + 1 < T_DIM) {
            uint4 xh, xl;
            split8(xv, xh, xl);
            *(uint4*)(smc + OFF_AHI + offx) = xh;
            *(uint4*)(smc + OFF_ALO + offx) = xl;

            uint4 hh = *(uint4*)(smc + OFF_SHI + prow * 128 + pj * 16);
            uint4 hl = *(uint4*)(smc + OFF_SLO + prow * 128 + pj * 16);
            *(uint4*)(smc + OFF_AHI + offh) = hh;
            *(uint4*)(smc + OFF_ALO + offh) = hl;
            st_rem64(peerAhi,     (u64)hh.x | ((u64)hh.y << 32));
            st_rem64(peerAhi + 8, (u64)hh.z | ((u64)hh.w << 32));
            st_rem64(peerAlo,     (u64)hl.x | ((u64)hl.y << 32));
            st_rem64(peerAlo + 8, (u64)hl.z | ((u64)hl.w << 32));
        }
    }
    csync();    // drain in-flight remote stores before exit
}

extern "C" void kernel_launch(void* const* d_in, const int* in_sizes, int n_in,
                              void* d_out, int out_size) {
    const float* x  = (const float*)d_in[0];   // [B,T,F]
    const float* Wx = (const float*)d_in[1];   // [F,512]
    const float* Wh = (const float*)d_in[2];   // [H,512]
    const float* b  = (const float*)d_in[3];   // [512]
    float* out = (float*)d_out;                // [B,T,H]

    cudaFuncSetAttribute(lstm_mma, cudaFuncAttributeMaxDynamicSharedMemorySize, SMEM_TOTAL);
    lstm_mma<<<128, NTH, SMEM_TOTAL>>>(x, Wx, Wh, b, out);
}